// round 14
// baseline (speedup 1.0000x reference)
#include <cuda_runtime.h>
#include <cuda_fp16.h>
#include <cstdint>

// KANLinear, round 14: packed K = 512*7 = 3584 (no zero k-slot). 16 feats =
// 112 k = 7 ksteps of 16, so the GEMM only changes NKSTEP (256 -> 224).
// btf builds B frags with f=k/7, m=k%7. afln generates two features per
// lane (7 conflict-free STS.32 into linear staging) then assembles frags
// (4 LDS.32 + STG.128, slot=lane stored at SIG(lane) — byte-equivalent
// layout to all passing rounds).

#define NROWS 32768
#define FDIM  512
#define UDIM  512
#define KW     7
#define NKSTEP 224                  // 16-k steps

#define BIG    4
#define NIT    (NKSTEP / BIG)       // 56
#define STG_BYTES 32768             // 16KB A + 16KB B
#define NSTG   3
#define SMEM_TOTAL (NSTG * STG_BYTES)

__device__ __half g_btf[(size_t)64 * NKSTEP * 32 * 4];    // 3.5 MB B frags
__device__ __half g_af [(size_t)2048 * NKSTEP * 32 * 8];  // 224 MB A frags

#define SIG(L) ((((L) & 3) << 3) | (((L) >> 2) ^ ((((L) & 3) << 1) & 7)))

__device__ __forceinline__ uint32_t smem_u32(const void* p) {
    uint32_t a;
    asm("{ .reg .u64 t; cvta.to.shared.u64 t, %1; cvt.u32.u64 %0, t; }"
        : "=r"(a) : "l"(p));
    return a;
}
#define CP_ASYNC16(dst_u32, src_ptr) \
    asm volatile("cp.async.cg.shared.global [%0], [%1], 16;" \
                 :: "r"(dst_u32), "l"(src_ptr) : "memory")
#define CP_COMMIT() asm volatile("cp.async.commit_group;" ::: "memory")
#define CP_WAIT1()  asm volatile("cp.async.wait_group 1;" ::: "memory")

// ---------------------------------------------------------------------------
// Kernel 1: B fragments, packed K. Thread = output column n; block handles
// one kstep. k = ks*16 + kk; f = k/7, m = k%7; m==0 -> Wb, else Ws.
// ---------------------------------------------------------------------------
__global__ __launch_bounds__(256) void btf_kernel(const float* __restrict__ Wb,
                                                  const float* __restrict__ Ws) {
    const int n  = blockIdx.x * 256 + threadIdx.x;
    const int ks = blockIdx.y;
    float v[16];
    #pragma unroll
    for (int kk = 0; kk < 16; ++kk) {
        int k = ks * 16 + kk;
        int f = k / KW;
        int m = k - f * KW;
        v[kk] = (m == 0) ? Wb[(size_t)f * UDIM + n]
                         : Ws[(size_t)(f * 6 + m - 1) * UDIM + n];
    }
    __half2* dst = reinterpret_cast<__half2*>(g_btf);
    size_t base = (((size_t)(n >> 3) * NKSTEP + ks) * 32 + (n & 7) * 4) * 2;
    #pragma unroll
    for (int t = 0; t < 4; ++t) {
        dst[base + t * 2 + 0] = __floats2half2_rn(v[2 * t],     v[2 * t + 1]);
        dst[base + t * 2 + 1] = __floats2half2_rn(v[8 + 2 * t], v[8 + 2 * t + 1]);
    }
}

// ---------------------------------------------------------------------------
// closed-form cubic B-spline: 7 values (relu, b3[0..5])
// ---------------------------------------------------------------------------
__device__ __forceinline__ void gen7(float xv, float t0, float inv_h, float* v) {
    float xr = (xv - t0) * inv_h;
    float fi = floorf(xr);
    int   i  = (int)fi;
    float s  = xr - fi;
    float s2 = s * s, s3 = s2 * s;
    float u  = 1.0f - s;
    const float c6 = 1.0f / 6.0f;
    float B0 = c6 * u * u * u;
    float B1 = c6 * (3.0f * s3 - 6.0f * s2 + 4.0f);
    float B2 = c6 * (-3.0f * s3 + 3.0f * s2 + 3.0f * s + 1.0f);
    float B3 = c6 * s3;
    bool valid = (xr >= 0.0f) && (i <= 8);
    v[0] = fmaxf(xv, 0.0f);
    #pragma unroll
    for (int j = 0; j < 6; ++j) {
        int d = i - j;
        float bv = (d == 3) ? B0 : (d == 2) ? B1 : (d == 1) ? B2 : (d == 0) ? B3 : 0.0f;
        v[1 + j] = valid ? bv : 0.0f;
    }
}

// ---------------------------------------------------------------------------
// Kernel 2: fused LN + packed A fragments.
// Block = 256 thr = 8 warps; one block per 16-row group.
// Per warp: 4 feature-groups of 16 feats (= 7 ksteps each).
//  Phase A: lane (rl=lane&15, ph=lane>>4) gen7 for features {4q+2ph, +1},
//           writes 7 STS.32 into linear staging row (stride 116 halves --
//           conflict-free: banks 26*rl (all evens) + 7*ph (odd shift)).
//  Phase B: lane assembles logical slot 'lane' (g7=lane>>2, t=lane&3) with
//           4 LDS.32: (g7,2t),(g7+8,2t),(g7,8+2t),(g7+8,8+2t) of kstep j,
//           STG.128 at position SIG(lane) -- byte-identical layout.
// ---------------------------------------------------------------------------
__global__ __launch_bounds__(256) void afln_kernel(
    const float* __restrict__ x,
    const float* __restrict__ gamma,
    const float* __restrict__ beta,
    const float* __restrict__ grid_knots)
{
    __shared__ float sx[16][514];
    __shared__ float sg[512], sb[512];
    __shared__ float smean[16], sinv[16];
    __shared__ __align__(16) __half sstg[8][16 * 116];   // 29696 B

    const int tid  = threadIdx.x;
    const int lane = tid & 31;
    const int wq   = tid >> 5;
    const int R0   = blockIdx.x * 16;

    const float t0    = __ldg(grid_knots);
    const float inv_h = 1.0f / (__ldg(grid_knots + 1) - t0);

    // ---- stage raw x + gamma/beta ----
    for (int idx = tid; idx < 16 * 128; idx += 256) {
        int row = idx >> 7, q = idx & 127;
        float4 v = __ldg(reinterpret_cast<const float4*>(
            x + (size_t)(R0 + row) * FDIM) + q);
        *reinterpret_cast<float2*>(&sx[row][q * 4])     = make_float2(v.x, v.y);
        *reinterpret_cast<float2*>(&sx[row][q * 4 + 2]) = make_float2(v.z, v.w);
    }
    for (int idx = tid; idx < 512; idx += 256) {
        sg[idx] = __ldg(gamma + idx);
        sb[idx] = __ldg(beta + idx);
    }
    __syncthreads();

    // ---- LN stats: warp wq handles rows 2wq, 2wq+1 ----
    #pragma unroll
    for (int rr = 0; rr < 2; ++rr) {
        int r = wq * 2 + rr;
        float s = 0.0f;
        #pragma unroll
        for (int i = 0; i < 16; ++i) s += sx[r][lane + 32 * i];
        #pragma unroll
        for (int o = 16; o > 0; o >>= 1) s += __shfl_xor_sync(~0u, s, o);
        float mean = s * (1.0f / FDIM);
        float s2 = 0.0f;
        #pragma unroll
        for (int i = 0; i < 16; ++i) {
            float d = sx[r][lane + 32 * i] - mean;
            s2 += d * d;
        }
        #pragma unroll
        for (int o = 16; o > 0; o >>= 1) s2 += __shfl_xor_sync(~0u, s2, o);
        if (lane == 0) {
            smean[r] = mean;
            sinv[r]  = rsqrtf(s2 * (1.0f / FDIM) + 1e-3f);
        }
    }
    __syncthreads();

    const int rl = lane & 15;
    const int ph = lane >> 4;
    const int g7 = lane >> 2;
    const int tq = lane & 3;
    const float mean = smean[rl];
    const float inv  = sinv[rl];

    __half* stg = &sstg[wq][rl * 116];
    const __half* stgW = sstg[wq];
    uint4* dstB = reinterpret_cast<uint4*>(g_af) +
                  (size_t)blockIdx.x * NKSTEP * 32 + SIG(lane);

    #pragma unroll 1
    for (int g = wq; g < 32; g += 8) {        // 4 feature groups of 16
        // ---- phase A: generate ----
        #pragma unroll
        for (int q = 0; q < 4; ++q) {
            int fp  = q * 4 + ph * 2;          // even feature pair base
            int col = g * 16 + fp;
            float xa = (sx[rl][col]     - mean) * inv * sg[col]     + sb[col];
            float xb = (sx[rl][col + 1] - mean) * inv * sg[col + 1] + sb[col + 1];
            float va[7], vb[7];
            gen7(xa, t0, inv_h, va);
            gen7(xb, t0, inv_h, vb);
            __half2* w = reinterpret_cast<__half2*>(stg + fp * KW);
            w[0] = __floats2half2_rn(va[0], va[1]);
            w[1] = __floats2half2_rn(va[2], va[3]);
            w[2] = __floats2half2_rn(va[4], va[5]);
            w[3] = __floats2half2_rn(va[6], vb[0]);
            w[4] = __floats2half2_rn(vb[1], vb[2]);
            w[5] = __floats2half2_rn(vb[3], vb[4]);
            w[6] = __floats2half2_rn(vb[5], vb[6]);
        }
        __syncwarp();
        // ---- phase B: assemble fragments ----
        #pragma unroll
        for (int j = 0; j < KW; ++j) {
            int kl = j * 16 + 2 * tq;
            uint32_t w0 = *reinterpret_cast<const uint32_t*>(&stgW[g7 * 116 + kl]);
            uint32_t w1 = *reinterpret_cast<const uint32_t*>(&stgW[(g7 + 8) * 116 + kl]);
            uint32_t w2 = *reinterpret_cast<const uint32_t*>(&stgW[g7 * 116 + kl + 8]);
            uint32_t w3 = *reinterpret_cast<const uint32_t*>(&stgW[(g7 + 8) * 116 + kl + 8]);
            dstB[(size_t)(g * KW + j) * 32] = make_uint4(w0, w1, w2, w3);
        }
        __syncwarp();
    }
}

// ---------------------------------------------------------------------------
// Kernel 3: cp.async 3-stage pipelined HMMA GEMM (round-10 structure,
// NKSTEP=224 / NIT=56 only change).
// ---------------------------------------------------------------------------
__global__ __launch_bounds__(256, 2) void kan_mma_kernel(
    const float* __restrict__ bias, float* __restrict__ out)
{
    extern __shared__ __align__(16) char smem[];
    const uint32_t sbase = smem_u32(smem);

    const int tid  = threadIdx.x;
    const int lane = tid & 31;
    const int wid  = tid >> 5;
    const int wm   = wid >> 2;
    const int wn   = wid & 3;
    const int row0 = blockIdx.y * 128;
    const int col0 = blockIdx.x * 128;

    const uint4* agm = reinterpret_cast<const uint4*>(g_af);
    const uint4* bgm = reinterpret_cast<const uint4*>(g_btf);
    const size_t arow0 = (size_t)blockIdx.y * 8;
    const size_t brow0 = (size_t)blockIdx.x * 16;

    auto issue_stage = [&](int stg, int ks0) {
        const uint32_t da = sbase + stg * STG_BYTES;
        const uint32_t db = da + 16384;
        #pragma unroll
        for (int r = 0; r < 4; ++r) {
            int q = tid + r * 256;
            const uint4* srcA = agm +
                ((arow0 + (q >> 7)) * NKSTEP + ks0 + ((q >> 5) & 3)) * 32 + (q & 31);
            CP_ASYNC16(da + q * 16, srcA);
        }
        #pragma unroll
        for (int r = 0; r < 4; ++r) {
            int q = tid + r * 256;
            const uint4* srcB = bgm +
                ((brow0 + (q >> 6)) * NKSTEP + ks0 + ((q >> 4) & 3)) * 16 + (q & 15);
            CP_ASYNC16(db + q * 16, srcB);
        }
        CP_COMMIT();
    };

    float acc[4][4][4];
    #pragma unroll
    for (int in = 0; in < 4; ++in) {
        float2 bb = *reinterpret_cast<const float2*>(
            bias + col0 + wn * 32 + in * 8 + (lane & 3) * 2);
        #pragma unroll
        for (int im = 0; im < 4; ++im) {
            acc[im][in][0] = bb.x; acc[im][in][1] = bb.y;
            acc[im][in][2] = bb.x; acc[im][in][3] = bb.y;
        }
    }

    issue_stage(0, 0);
    issue_stage(1, BIG);

    const int aslot = SIG(lane);
    int stg = 0;
    for (int it = 0; it < NIT; ++it) {
        CP_WAIT1();
        __syncthreads();
        if (it + 2 < NIT) issue_stage((stg + 2) % NSTG, (it + 2) * BIG);

        const char* sa = smem + stg * STG_BYTES;
        const char* sb = sa + 16384;
        #pragma unroll
        for (int ks = 0; ks < BIG; ++ks) {
            uint4 a[4];
            #pragma unroll
            for (int im = 0; im < 4; ++im)
                a[im] = *reinterpret_cast<const uint4*>(
                    sa + (((wm * 4 + im) * 4 + ks) * 32 + aslot) * 16);
            uint2 b[4];
            #pragma unroll
            for (int in = 0; in < 4; ++in)
                b[in] = *reinterpret_cast<const uint2*>(
                    sb + (((wn * 4 + in) * 4 + ks) * 32 + lane) * 8);
            #pragma unroll
            for (int im = 0; im < 4; ++im)
                #pragma unroll
                for (int in = 0; in < 4; ++in) {
                    asm volatile(
                        "mma.sync.aligned.m16n8k16.row.col.f32.f16.f16.f32 "
                        "{%0,%1,%2,%3}, {%4,%5,%6,%7}, {%8,%9}, {%0,%1,%2,%3};"
                        : "+f"(acc[im][in][0]), "+f"(acc[im][in][1]),
                          "+f"(acc[im][in][2]), "+f"(acc[im][in][3])
                        : "r"(a[im].x), "r"(a[im].y), "r"(a[im].z), "r"(a[im].w),
                          "r"(b[in].x), "r"(b[in].y));
                }
        }
        stg = (stg + 1) % NSTG;
    }

    const int g  = lane >> 2;
    const int tq = lane & 3;
    #pragma unroll
    for (int im = 0; im < 4; ++im) {
        int row = row0 + wm * 64 + im * 16 + g;
        #pragma unroll
        for (int in = 0; in < 4; ++in) {
            int col = col0 + wn * 32 + in * 8 + tq * 2;
            *reinterpret_cast<float2*>(out + (size_t)row * UDIM + col)
                = make_float2(acc[im][in][0], acc[im][in][1]);
            *reinterpret_cast<float2*>(out + (size_t)(row + 8) * UDIM + col)
                = make_float2(acc[im][in][2], acc[im][in][3]);
        }
    }
}

// ---------------------------------------------------------------------------
extern "C" void kernel_launch(void* const* d_in, const int* in_sizes, int n_in,
                              void* d_out, int out_size) {
    const float* x     = (const float*)d_in[0];
    const float* gamma = (const float*)d_in[1];
    const float* beta  = (const float*)d_in[2];
    const float* Wb    = (const float*)d_in[3];
    const float* bias  = (const float*)d_in[4];
    const float* Ws    = (const float*)d_in[5];
    const float* grid  = (const float*)d_in[6];
    float* out = (float*)d_out;

    cudaFuncSetAttribute(kan_mma_kernel,
                         cudaFuncAttributeMaxDynamicSharedMemorySize, SMEM_TOTAL);

    btf_kernel<<<dim3(2, NKSTEP), 256>>>(Wb, Ws);
    afln_kernel<<<NROWS / 16, 256>>>(x, gamma, beta, grid);
    kan_mma_kernel<<<dim3(UDIM / 128, NROWS / 128), 256, SMEM_TOTAL>>>(bias, out);
}